// round 6
// baseline (speedup 1.0000x reference)
#include <cuda_runtime.h>
#include <math.h>
#include <stdint.h>

// ---------------------------------------------------------------------------
// FrameTransformer: B=1, C=8, F=1024, W=512, H=16, D=64, EXP=4
// Round 6: resubmit R5 (fused attention + R4 cp.async tf32 GEMMs).
// R5 bench was an infra flake (failed identically on known-good code in R2).
// ---------------------------------------------------------------------------

#define CC 8
#define FF 1024
#define WW 512
#define HH 16
#define DD 64
#define EXPAND 4
#define FHID (FF * EXPAND)   // 4096
#define NELEM (CC * FF * WW) // 4,194,304

// Scratch (device globals; no runtime allocation allowed)
__device__ float g_z[NELEM];                 // LN output
__device__ float g_p[NELEM];                 // P = Wq @ z  (also V)
__device__ float g_q[NELEM];                 // RoPE(P) (q == k)
__device__ float g_o[NELEM];                 // attention output (pre-Wo)
__device__ float g_h[CC * FHID * WW];        // MLP hidden (67 MB)

#define MMA_TF32(C, A, B)                                                     \
    asm volatile(                                                             \
        "mma.sync.aligned.m16n8k8.row.col.f32.tf32.tf32.f32 "                 \
        "{%0,%1,%2,%3}, {%4,%5,%6,%7}, {%8,%9}, {%0,%1,%2,%3};"               \
        : "+f"((C)[0]), "+f"((C)[1]), "+f"((C)[2]), "+f"((C)[3])              \
        : "r"((A)[0]), "r"((A)[1]), "r"((A)[2]), "r"((A)[3]),                 \
          "r"((B)[0]), "r"((B)[1]))

__device__ __forceinline__ void cp16(uint32_t dst, const void* src) {
    asm volatile("cp.async.cg.shared.global [%0], [%1], 16;" :: "r"(dst), "l"(src));
}
#define CP_COMMIT() asm volatile("cp.async.commit_group;")

// ---------------------------------------------------------------------------
// Frame norm over F for each (c, w) column. x layout: [C][F][W]
// ---------------------------------------------------------------------------
__global__ void ln_kernel(const float* __restrict__ x,
                          const float* __restrict__ g,
                          const float* __restrict__ b,
                          float* __restrict__ z)
{
    const int c  = blockIdx.y;
    const int w  = blockIdx.x * 32 + threadIdx.x;
    const int ty = threadIdx.y;
    const float* xc = x + (size_t)c * FF * WW;
    float*       zc = z + (size_t)c * FF * WW;

    float sum = 0.f, sq = 0.f;
    for (int f = ty; f < FF; f += 8) {
        float v = xc[(size_t)f * WW + w];
        sum += v;
        sq  = fmaf(v, v, sq);
    }
    __shared__ float s_sum[8][32];
    __shared__ float s_sq[8][32];
    s_sum[ty][threadIdx.x] = sum;
    s_sq[ty][threadIdx.x]  = sq;
    __syncthreads();
    if (ty == 0) {
        #pragma unroll
        for (int i = 1; i < 8; ++i) {
            sum += s_sum[i][threadIdx.x];
            sq  += s_sq[i][threadIdx.x];
        }
        float mu  = sum * (1.0f / FF);
        float var = sq * (1.0f / FF) - mu * mu;
        s_sum[0][threadIdx.x] = mu;
        s_sq[0][threadIdx.x]  = rsqrtf(var + 1e-5f);
    }
    __syncthreads();
    const float mu   = s_sum[0][threadIdx.x];
    const float rinv = s_sq[0][threadIdx.x];
    for (int f = ty; f < FF; f += 8) {
        float v = xc[(size_t)f * WW + w];
        zc[(size_t)f * WW + w] = (v - mu) * rinv * g[f] + b[f];
    }
}

// ---------------------------------------------------------------------------
// Tensor-core batched GEMM: Out[c] = W[c] @ In[c]
// MODE 0: store; 1: store + Res; 2: store gelu(acc); 3: Out += acc
// 256 thr, tile 128x128, warp 64x32, BK=16, tf32 mma, 2-stage cp.async.
// ---------------------------------------------------------------------------
template <int MODE>
__global__ __launch_bounds__(256)
void tgemm_kernel(const float* __restrict__ Wt, const float* __restrict__ In,
                  float* __restrict__ Out, const float* __restrict__ Res,
                  int M, int K)
{
    const int c = blockIdx.z;
    Wt  += (size_t)c * M * K;
    In  += (size_t)c * K * WW;
    Out += (size_t)c * M * WW;
    if (MODE == 1) Res += (size_t)c * M * WW;

    __shared__ float As[2][128][20];   // [stage][m][k]
    __shared__ float Bs[2][16][136];   // [stage][k][n]

    const int tid  = threadIdx.x;
    const int lane = tid & 31;
    const int wid  = tid >> 5;
    const int m0   = blockIdx.y * 128;
    const int n0   = blockIdx.x * 128;
    const int wm   = (wid >> 2) * 64;
    const int wn   = (wid & 3) * 32;
    const int lg   = lane >> 2;
    const int lt   = lane & 3;

    const int a_row = tid >> 2;
    const int a_kc  = (tid & 3) * 4;
    const int b_row = tid >> 5;
    const int b_nc  = (tid & 31) * 4;

    const float* Apg = Wt + (size_t)(m0 + a_row) * K + a_kc;
    const float* Bpg = In + n0 + b_nc;

    const int KT = K >> 4;

    {
        cp16(__cvta_generic_to_shared(&As[0][a_row][a_kc]),      Apg);
        cp16(__cvta_generic_to_shared(&As[0][a_row + 64][a_kc]), Apg + (size_t)64 * K);
        cp16(__cvta_generic_to_shared(&Bs[0][b_row][b_nc]),      Bpg + (size_t)b_row * WW);
        cp16(__cvta_generic_to_shared(&Bs[0][b_row + 8][b_nc]),  Bpg + (size_t)(b_row + 8) * WW);
        CP_COMMIT();
    }

    float acc[4][4][4];
    #pragma unroll
    for (int mi = 0; mi < 4; ++mi)
        #pragma unroll
        for (int ni = 0; ni < 4; ++ni)
            #pragma unroll
            for (int r = 0; r < 4; ++r) acc[mi][ni][r] = 0.f;

    for (int kt = 0; kt < KT; ++kt) {
        if (kt + 1 < KT) {
            const int s  = (kt + 1) & 1;
            const int k0 = (kt + 1) << 4;
            cp16(__cvta_generic_to_shared(&As[s][a_row][a_kc]),      Apg + k0);
            cp16(__cvta_generic_to_shared(&As[s][a_row + 64][a_kc]), Apg + (size_t)64 * K + k0);
            cp16(__cvta_generic_to_shared(&Bs[s][b_row][b_nc]),      Bpg + (size_t)(k0 + b_row) * WW);
            cp16(__cvta_generic_to_shared(&Bs[s][b_row + 8][b_nc]),  Bpg + (size_t)(k0 + b_row + 8) * WW);
            CP_COMMIT();
            asm volatile("cp.async.wait_group 1;");
        } else {
            asm volatile("cp.async.wait_group 0;");
        }
        __syncthreads();

        const int buf = kt & 1;
        #pragma unroll
        for (int ks = 0; ks < 2; ++ks) {
            const int kb = ks * 8 + lt;
            uint32_t a[4][4];
            #pragma unroll
            for (int mi = 0; mi < 4; ++mi) {
                const int m = wm + mi * 16 + lg;
                a[mi][0] = __float_as_uint(As[buf][m][kb]);
                a[mi][1] = __float_as_uint(As[buf][m + 8][kb]);
                a[mi][2] = __float_as_uint(As[buf][m][kb + 4]);
                a[mi][3] = __float_as_uint(As[buf][m + 8][kb + 4]);
            }
            uint32_t bfr[4][2];
            #pragma unroll
            for (int ni = 0; ni < 4; ++ni) {
                const int n = wn + ni * 8 + lg;
                bfr[ni][0] = __float_as_uint(Bs[buf][kb][n]);
                bfr[ni][1] = __float_as_uint(Bs[buf][kb + 4][n]);
            }
            #pragma unroll
            for (int mi = 0; mi < 4; ++mi)
                #pragma unroll
                for (int ni = 0; ni < 4; ++ni)
                    MMA_TF32(acc[mi][ni], a[mi], bfr[ni]);
        }
        __syncthreads();
    }

    #pragma unroll
    for (int mi = 0; mi < 4; ++mi) {
        const int r0 = m0 + wm + mi * 16 + lg;
        #pragma unroll
        for (int ni = 0; ni < 4; ++ni) {
            const int cc = n0 + wn + ni * 8 + lt * 2;
            #pragma unroll
            for (int half = 0; half < 2; ++half) {
                const int row = r0 + half * 8;
                const size_t idx = (size_t)row * WW + cc;
                float v0 = acc[mi][ni][half * 2 + 0];
                float v1 = acc[mi][ni][half * 2 + 1];
                if (MODE == 1) {
                    float2 rv = *(const float2*)(Res + idx);
                    v0 += rv.x; v1 += rv.y;
                } else if (MODE == 2) {
                    v0 = 0.5f * v0 * (1.0f + erff(v0 * 0.70710678118654752f));
                    v1 = 0.5f * v1 * (1.0f + erff(v1 * 0.70710678118654752f));
                } else if (MODE == 3) {
                    float2 rv = *(const float2*)(Out + idx);
                    v0 += rv.x; v1 += rv.y;
                }
                *(float2*)(Out + idx) = make_float2(v0, v1);
            }
        }
    }
}

// ---------------------------------------------------------------------------
// RoPE: q[c, h*64+d, w]. First 32 dims of each head rotated (interleaved).
// ---------------------------------------------------------------------------
__global__ void rope_kernel(const float* __restrict__ p,
                            const float* __restrict__ freqs,
                            float* __restrict__ q)
{
    int n = blockIdx.x * blockDim.x + threadIdx.x;
    if (n >= NELEM) return;
    const int w = n & (WW - 1);
    const int f = (n >> 9) & (FF - 1);
    const int d = f & (DD - 1);
    float v = p[n];
    if (d >= 32) { q[n] = v; return; }
    const int j = d >> 1;
    const float ang = (float)w * freqs[j];
    const float cs = cosf(ang);
    const float sn = sinf(ang);
    if ((d & 1) == 0) {
        float v2 = p[n + WW];
        q[n] = v * cs - v2 * sn;
    } else {
        float v2 = p[n - WW];
        q[n] = v * cs + v2 * sn;
    }
}

// ---------------------------------------------------------------------------
// Fused attention: per (head ch = blockIdx.y, q-tile 64 = blockIdx.x*64).
// Stage A: S[64][512] strip in smem via tf32 MMA (Q^T Q, scaled).
// Stage B: softmax over smem rows.
// Stage C: O[q][d] = P @ V^T via tf32 MMA, written transposed to O slab.
// Dynamic smem layout (floats):
//   Qs[64][68]                               (17408 B)
//   KV: union{ Ks[64][132] | Vs[128][68] }   (34816 B)
//   Ss[64][520]                              (133120 B)
// ---------------------------------------------------------------------------
#define ATTN_SMEM_BYTES ((64 * 68 + 128 * 68 + 64 * 520) * 4)

__global__ __launch_bounds__(256)
void fused_attn_kernel(const float* __restrict__ Qg,
                       const float* __restrict__ Vg,
                       float* __restrict__ Og)
{
    extern __shared__ float smem[];
    float (*Qs)[68]  = (float(*)[68])smem;                 // [d][q]
    float (*Ks)[132] = (float(*)[132])(smem + 64 * 68);    // [d][k]
    float (*Vs)[68]  = (float(*)[68])(smem + 64 * 68);     // [k][d] (reuse)
    float (*Ss)[520] = (float(*)[520])(smem + 64 * 68 + 128 * 68);

    const int ch = blockIdx.y;
    const size_t hoff = (size_t)((ch >> 4) * FF + (ch & 15) * DD) * WW;
    const float* Q = Qg + hoff;    // [64][512]
    const float* V = Vg + hoff;    // [64][512]
    float*       O = Og + hoff;    // [64][512]
    const int q0 = blockIdx.x * 64;

    const int tid  = threadIdx.x;
    const int lane = tid & 31;
    const int wid  = tid >> 5;
    const int lg   = lane >> 2;
    const int lt   = lane & 3;

    // ---- load Q tile [d=64][q=64] ----
    {
        const int row = tid >> 2;
        const int cb  = (tid & 3) * 16;
        const float* Qr = Q + (size_t)row * WW + q0 + cb;
        #pragma unroll
        for (int c = 0; c < 4; ++c)
            *(float4*)&Qs[row][cb + 4 * c] = *(const float4*)(Qr + 4 * c);
    }

    // ================= Stage A: scores =================
    const int wmA = (wid >> 1) * 16;       // q offset within tile
    const int wnA = (wid & 1) * 64;        // k offset within k-tile
    const float scale = 1.0f / 32.0f;

    for (int kt = 0; kt < 4; ++kt) {
        __syncthreads();   // protect Ks reuse from previous iter's consumers
        {
            const int row = tid >> 2;
            const int cb  = (tid & 3) * 32;
            const float* Kr = Q + (size_t)row * WW + kt * 128 + cb;
            #pragma unroll
            for (int c = 0; c < 8; ++c)
                *(float4*)&Ks[row][cb + 4 * c] = *(const float4*)(Kr + 4 * c);
        }
        __syncthreads();

        float acc[8][4];
        #pragma unroll
        for (int ni = 0; ni < 8; ++ni)
            #pragma unroll
            for (int r = 0; r < 4; ++r) acc[ni][r] = 0.f;

        #pragma unroll
        for (int dd = 0; dd < 64; dd += 8) {
            const int kb = dd + lt;
            uint32_t a[4];
            a[0] = __float_as_uint(Qs[kb][wmA + lg]);
            a[1] = __float_as_uint(Qs[kb][wmA + lg + 8]);
            a[2] = __float_as_uint(Qs[kb + 4][wmA + lg]);
            a[3] = __float_as_uint(Qs[kb + 4][wmA + lg + 8]);
            uint32_t bf[8][2];
            #pragma unroll
            for (int ni = 0; ni < 8; ++ni) {
                const int n = wnA + ni * 8 + lg;
                bf[ni][0] = __float_as_uint(Ks[kb][n]);
                bf[ni][1] = __float_as_uint(Ks[kb + 4][n]);
            }
            #pragma unroll
            for (int ni = 0; ni < 8; ++ni)
                MMA_TF32(acc[ni], a, bf[ni]);
        }

        // store scaled scores into Ss
        #pragma unroll
        for (int ni = 0; ni < 8; ++ni) {
            const int col = kt * 128 + wnA + ni * 8 + lt * 2;
            *(float2*)&Ss[wmA + lg][col] =
                make_float2(acc[ni][0] * scale, acc[ni][1] * scale);
            *(float2*)&Ss[wmA + lg + 8][col] =
                make_float2(acc[ni][2] * scale, acc[ni][3] * scale);
        }
    }
    __syncthreads();

    // ================= Stage B: softmax (smem) =================
    for (int r = wid; r < 64; r += 8) {
        float v[16];
        float mx = -1e30f;
        #pragma unroll
        for (int i = 0; i < 16; ++i) {
            v[i] = Ss[r][lane + i * 32];
            mx = fmaxf(mx, v[i]);
        }
        #pragma unroll
        for (int o = 16; o > 0; o >>= 1)
            mx = fmaxf(mx, __shfl_xor_sync(0xFFFFFFFFu, mx, o));
        float sum = 0.f;
        #pragma unroll
        for (int i = 0; i < 16; ++i) {
            v[i] = expf(v[i] - mx);
            sum += v[i];
        }
        #pragma unroll
        for (int o = 16; o > 0; o >>= 1)
            sum += __shfl_xor_sync(0xFFFFFFFFu, sum, o);
        const float inv = 1.0f / sum;
        #pragma unroll
        for (int i = 0; i < 16; ++i) Ss[r][lane + i * 32] = v[i] * inv;
    }

    // ================= Stage C: O = P @ V^T =================
    const int wmC = (wid >> 1) * 16;       // q offset
    const int wnC = (wid & 1) * 32;        // d offset

    float accO[4][4];
    #pragma unroll
    for (int ni = 0; ni < 4; ++ni)
        #pragma unroll
        for (int r = 0; r < 4; ++r) accO[ni][r] = 0.f;

    for (int kt = 0; kt < 4; ++kt) {
        __syncthreads();   // Ss ready (1st iter) / Vs consumers done (later)
        {
            // load V tile transposed: Vs[k][d] from V[d][kt*128 + k]
            const int row = tid >> 2;              // d
            const int kb0 = (tid & 3) * 32;        // k base
            const float* Vr = V + (size_t)row * WW + kt * 128 + kb0;
            #pragma unroll
            for (int c = 0; c < 8; ++c) {
                float4 pv = *(const float4*)(Vr + 4 * c);
                const int k = kb0 + 4 * c;
                Vs[k + 0][row] = pv.x;
                Vs[k + 1][row] = pv.y;
                Vs[k + 2][row] = pv.z;
                Vs[k + 3][row] = pv.w;
            }
        }
        __syncthreads();

        #pragma unroll 4
        for (int ks = 0; ks < 16; ++ks) {
            const int kb = ks * 8 + lt;            // local k in tile
            const int kc = kt * 128 + kb;          // global k column in Ss
            uint32_t a[4];
            a[0] = __float_as_uint(Ss[wmC + lg][kc]);
            a[1] = __float_as_uint(Ss[wmC + lg + 8][kc]);
            a[2] = __float_as_uint(Ss[wmC + lg][kc + 4]);
            a[3] = __float_as_uint(Ss[wmC + lg + 8][kc + 4]);
            uint32_t bf[4][2];
            #pragma unroll
            for (int ni = 0; ni < 4; ++ni) {
                const int n = wnC + ni * 8 + lg;
                bf[ni][0] = __float_as_uint(Vs[kb][n]);
                bf[ni][1] = __float_as_uint(Vs[kb + 4][n]);
            }
            #pragma unroll
            for (int ni = 0; ni < 4; ++ni)
                MMA_TF32(accO[ni], a, bf[ni]);
        }
    }

    // epilogue: O[d][q] = accO (transposed store)
    #pragma unroll
    for (int ni = 0; ni < 4; ++ni) {
        const int d0 = wnC + ni * 8 + lt * 2;
        const int qq = q0 + wmC + lg;
        O[(size_t)(d0 + 0) * WW + qq]     = accO[ni][0];
        O[(size_t)(d0 + 1) * WW + qq]     = accO[ni][1];
        O[(size_t)(d0 + 0) * WW + qq + 8] = accO[ni][2];
        O[(size_t)(d0 + 1) * WW + qq + 8] = accO[ni][3];
    }
}

// ---------------------------------------------------------------------------
// Launch
// ---------------------------------------------------------------------------
extern "C" void kernel_launch(void* const* d_in, const int* in_sizes, int n_in,
                              void* d_out, int out_size)
{
    const float* x   = (const float*)d_in[0];
    const float* n1g = (const float*)d_in[1];
    const float* n1b = (const float*)d_in[2];
    const float* wq  = (const float*)d_in[3];
    const float* wo  = (const float*)d_in[4];
    const float* rf  = (const float*)d_in[5];
    const float* n2g = (const float*)d_in[6];
    const float* n2b = (const float*)d_in[7];
    const float* w1  = (const float*)d_in[8];
    const float* w2  = (const float*)d_in[9];
    float* out = (float*)d_out;

    float *z, *p, *q, *o, *h;
    cudaGetSymbolAddress((void**)&z, g_z);
    cudaGetSymbolAddress((void**)&p, g_p);
    cudaGetSymbolAddress((void**)&q, g_q);
    cudaGetSymbolAddress((void**)&o, g_o);
    cudaGetSymbolAddress((void**)&h, g_h);

    cudaFuncSetAttribute(fused_attn_kernel,
                         cudaFuncAttributeMaxDynamicSharedMemorySize,
                         ATTN_SMEM_BYTES);

    dim3 lnBlock(32, 8), lnGrid(WW / 32, CC);

    // 1. z = LN1(x)
    ln_kernel<<<lnGrid, lnBlock>>>(x, n1g, n1b, z);
    // 2. p = Wq @ z
    tgemm_kernel<0><<<dim3(4, 8, CC), 256>>>(wq, z, p, nullptr, FF, FF);
    // 3. q = rope(p)
    rope_kernel<<<NELEM / 256, 256>>>(p, rf, q);
    // 4-6. fused attention: o = softmax(q^T q / 32) @ v
    fused_attn_kernel<<<dim3(8, CC * HH), 256, ATTN_SMEM_BYTES>>>(q, p, o);
    // 7. out = x + Wo @ o
    tgemm_kernel<1><<<dim3(4, 8, CC), 256>>>(wo, o, out, x, FF, FF);
    // 8. z = LN2(out)
    ln_kernel<<<lnGrid, lnBlock>>>(out, n2g, n2b, z);
    // 9. h = gelu(W1 @ z)
    tgemm_kernel<2><<<dim3(4, FHID / 128, CC), 256>>>(w1, z, h, nullptr, FHID, FF);
    // 10. out += W2 @ h
    tgemm_kernel<3><<<dim3(4, 8, CC), 256>>>(w2, h, out, nullptr, FF, FHID);
}